// round 15
// baseline (speedup 1.0000x reference)
#include <cuda_runtime.h>
#include <math.h>

#define DIMC   96
#define NTOK   49
#define PITCH  100
#define NTHR   192

// smem layout (floats)
#define XSP_OFF 0        // 64 x PITCH x float2 : (hi,lo) split A tile (x, later O)
#define QS_OFF  12800    // 49 x PITCH : q
#define KS_OFF  17700    // 49 x PITCH : k
#define VS_OFF  22600    // 49 x PITCH : v
#define SMEM_FLOATS 27500
#define SMEM_BYTES  (SMEM_FLOATS * 4)

typedef unsigned long long u64;
typedef unsigned int u32;

__device__ float  g_bias[3 * NTOK * NTOK];
// [phase(4)][ks(12)][nbg(12)][lane(32)] -> (b0hi, b1hi, b0lo, b1lo)
__device__ float4 g_wfrag[4 * 12 * 12 * 32];

__device__ __forceinline__ float tf32r(float a) {
    float r; asm("cvt.rna.tf32.f32 %0, %1;" : "=f"(r) : "f"(a)); return r;
}

// ---- packed fp32x2 helpers (attention core) ----
__device__ __forceinline__ void fma2(u64& d, u64 a, u64 b) {
    asm("fma.rn.f32x2 %0, %1, %2, %0;" : "+l"(d) : "l"(a), "l"(b));
}
__device__ __forceinline__ u64 add2(u64 a, u64 b) {
    u64 d; asm("add.rn.f32x2 %0, %1, %2;" : "=l"(d) : "l"(a), "l"(b)); return d;
}
__device__ __forceinline__ float hsum2(u64 v) {
    float lo, hi; asm("mov.b64 {%0, %1}, %2;" : "=f"(lo), "=f"(hi) : "l"(v));
    return lo + hi;
}
__device__ __forceinline__ u64 dup2(float x) {
    u64 r; asm("mov.b64 %0, {%1, %1};" : "=l"(r) : "f"(x)); return r;
}
__device__ __forceinline__ void upk2(u64 v, float& lo, float& hi) {
    asm("mov.b64 {%0, %1}, %2;" : "=f"(lo), "=f"(hi) : "l"(v));
}

// ---- m16n8k8 tf32 mma, D = A*B + D ----
__device__ __forceinline__ void mma8(float c[4], const u32 a[4], u32 b0, u32 b1) {
    asm volatile(
        "mma.sync.aligned.m16n8k8.row.col.f32.tf32.tf32.f32 "
        "{%0,%1,%2,%3}, {%4,%5,%6,%7}, {%8,%9}, {%0,%1,%2,%3};"
        : "+f"(c[0]), "+f"(c[1]), "+f"(c[2]), "+f"(c[3])
        : "r"(a[0]), "r"(a[1]), "r"(a[2]), "r"(a[3]), "r"(b0), "r"(b1));
}

// ---- prep: gather rpb bias + split weights into tf32 hi/lo fragment order ----
__global__ void prep_kernel(const float* __restrict__ rpb,
                            const int* __restrict__ rel,
                            const float* __restrict__ qkv_w,
                            const float* __restrict__ proj_w) {
    int i = blockIdx.x * blockDim.x + threadIdx.x;
    if (i < NTOK * NTOK) {
        int idx = rel[i];
        #pragma unroll
        for (int h = 0; h < 3; ++h)
            g_bias[h * (NTOK * NTOK) + i] = rpb[idx * 3 + h];
    }
    if (i < 4 * 12 * 12 * 32) {
        int lane = i & 31;
        int rest = i >> 5;          // 0..575
        int nbg  = rest % 12;
        int ks   = (rest / 12) % 12;
        int p    = rest / 144;      // 0..3
        const float* W = (p < 3) ? (qkv_w + p * DIMC * DIMC) : proj_w;
        int g = lane >> 2, t = lane & 3;
        int n = nbg * 8 + g;
        int k0 = ks * 8 + t;
        float b0 = W[n * DIMC + k0];
        float b1 = W[n * DIMC + k0 + 4];
        float h0 = tf32r(b0), h1 = tf32r(b1);
        float4 v;
        v.x = h0; v.y = h1;
        v.z = tf32r(b0 - h0); v.w = tf32r(b1 - h1);
        g_wfrag[i] = v;
    }
}

// ---- one 64x96x96 GEMM on tensor cores (3xTF32); A pre-split (hi,lo) ----
__device__ __forceinline__ void gemm64x96(
    const float2* __restrict__ xsp,    // A tile 64 x PITCH float2 (hi,lo), smem
    int slice,                          // 0..3 -> g_wfrag phase
    const float* __restrict__ bias,     // 96 biases (gmem)
    float scale,
    float* __restrict__ dst_smem,       // 49 x PITCH, or null
    float* __restrict__ dst_gmem,       // rows<49, ld 96, or null
    int wm, int wn, int g, int t, int lane) {

    float acc[2][4][4];
    #pragma unroll
    for (int a = 0; a < 2; ++a)
        #pragma unroll
        for (int b = 0; b < 4; ++b)
            #pragma unroll
            for (int c = 0; c < 4; ++c) acc[a][b][c] = 0.0f;

    const float4* wf = g_wfrag + slice * (12 * 12 * 32);

    float4 bpre[4];
    #pragma unroll
    for (int nb = 0; nb < 4; ++nb)
        bpre[nb] = wf[(wn * 4 + nb) * 32 + lane];

    #pragma unroll 2
    for (int ks = 0; ks < 12; ++ks) {
        float4 bcur[4];
        #pragma unroll
        for (int nb = 0; nb < 4; ++nb) bcur[nb] = bpre[nb];
        if (ks < 11) {
            #pragma unroll
            for (int nb = 0; nb < 4; ++nb)
                bpre[nb] = wf[((ks + 1) * 12 + wn * 4 + nb) * 32 + lane];
        }
        // A fragments: rows (wm*32+mb*16)+{g, g+8}, cols ks*8+{t, t+4}; no CVT
        u32 ah[2][4], al[2][4];
        #pragma unroll
        for (int mb = 0; mb < 2; ++mb) {
            const int r = wm * 32 + mb * 16 + g;
            const float2* xp = xsp + r * PITCH + ks * 8 + t;
            float2 a0 = xp[0];
            float2 a1 = xp[8 * PITCH];
            float2 a2 = xp[4];
            float2 a3 = xp[8 * PITCH + 4];
            ah[mb][0] = __float_as_uint(a0.x); al[mb][0] = __float_as_uint(a0.y);
            ah[mb][1] = __float_as_uint(a1.x); al[mb][1] = __float_as_uint(a1.y);
            ah[mb][2] = __float_as_uint(a2.x); al[mb][2] = __float_as_uint(a2.y);
            ah[mb][3] = __float_as_uint(a3.x); al[mb][3] = __float_as_uint(a3.y);
        }
        #pragma unroll
        for (int nb = 0; nb < 4; ++nb) {
            u32 b0h = __float_as_uint(bcur[nb].x), b1h = __float_as_uint(bcur[nb].y);
            u32 b0l = __float_as_uint(bcur[nb].z), b1l = __float_as_uint(bcur[nb].w);
            #pragma unroll
            for (int mb = 0; mb < 2; ++mb) {
                mma8(acc[mb][nb], ah[mb], b0h, b1h);   // hi*hi
                mma8(acc[mb][nb], ah[mb], b0l, b1l);   // hi*lo
                mma8(acc[mb][nb], al[mb], b0h, b1h);   // lo*hi
            }
        }
    }

    // epilogue: bias add, optional scale, guarded stores (rows < 49)
    #pragma unroll
    for (int mb = 0; mb < 2; ++mb) {
        #pragma unroll
        for (int nb = 0; nb < 4; ++nb) {
            const int r0 = wm * 32 + mb * 16 + g;
            const int c0 = wn * 32 + nb * 8 + (t << 1);
            float bx = bias[c0], by = bias[c0 + 1];
            float v00 = (acc[mb][nb][0] + bx) * scale;
            float v01 = (acc[mb][nb][1] + by) * scale;
            float v10 = (acc[mb][nb][2] + bx) * scale;
            float v11 = (acc[mb][nb][3] + by) * scale;
            if (dst_smem) {
                if (r0 < NTOK)     { dst_smem[r0 * PITCH + c0] = v00; dst_smem[r0 * PITCH + c0 + 1] = v01; }
                if (r0 + 8 < NTOK) { dst_smem[(r0 + 8) * PITCH + c0] = v10; dst_smem[(r0 + 8) * PITCH + c0 + 1] = v11; }
            } else {
                if (r0 < NTOK) {
                    float2 o; o.x = v00; o.y = v01;
                    *reinterpret_cast<float2*>(dst_gmem + r0 * DIMC + c0) = o;
                }
                if (r0 + 8 < NTOK) {
                    float2 o; o.x = v10; o.y = v11;
                    *reinterpret_cast<float2*>(dst_gmem + (r0 + 8) * DIMC + c0) = o;
                }
            }
        }
    }
}

__global__ void __launch_bounds__(NTHR, 2)
win_attn_kernel(const float* __restrict__ x,
                const float* __restrict__ mask,
                const float* __restrict__ qkv_b,
                const float* __restrict__ proj_b,
                float* __restrict__ out) {
    extern __shared__ float sm[];
    float2* xsp = reinterpret_cast<float2*>(sm + XSP_OFF); // (hi,lo) A tile
    float*  qsm = sm + QS_OFF;
    float*  ksm = sm + KS_OFF;
    float*  vsm = sm + VS_OFF;

    const int b    = blockIdx.x;
    const int wi   = b & 63;
    const int tid  = threadIdx.x;
    const int wid  = tid >> 5;
    const int lane = tid & 31;
    const int g    = lane >> 2;
    const int t    = lane & 3;
    const int wm   = wid & 1;      // 0..1
    const int wn   = wid >> 1;     // 0..2

    // ---- stage x with tf32 hi/lo split (49 real rows + 15 zero pad rows) ----
    const float* xg = x + (size_t)b * (NTOK * DIMC);
    for (int i = tid; i < NTOK * DIMC; i += NTHR) {
        float v = xg[i];
        float hi = tf32r(v);
        float2 p; p.x = hi; p.y = tf32r(v - hi);
        xsp[(i / DIMC) * PITCH + (i % DIMC)] = p;
    }
    for (int i = tid; i < 15 * DIMC; i += NTHR) {
        float2 z; z.x = 0.0f; z.y = 0.0f;
        xsp[(NTOK + i / DIMC) * PITCH + (i % DIMC)] = z;
    }
    __syncthreads();

    // ---- q, k, v GEMMs (tensor cores, no in-loop CVT) ----
    const float scale = 0.17677669529663687f;  // 32^-0.5
    gemm64x96(xsp, 0, qkv_b,       scale, qsm, nullptr, wm, wn, g, t, lane);
    gemm64x96(xsp, 1, qkv_b + 96,  1.0f,  ksm, nullptr, wm, wn, g, t, lane);
    gemm64x96(xsp, 2, qkv_b + 192, 1.0f,  vsm, nullptr, wm, wn, g, t, lane);
    __syncthreads();

    // ---- attention: scalar fp32, thread (n, h) owns one query row ----
    const int n = tid & 63;
    const int hh = tid >> 6;
    if (n < NTOK) {
        // q row -> packed regs
        u64 q2[16];
        {
            const ulonglong2* qrow =
                reinterpret_cast<const ulonglong2*>(qsm + n * PITCH + hh * 32);
            #pragma unroll
            for (int j = 0; j < 8; ++j) {
                ulonglong2 tq = qrow[j];
                q2[2*j] = tq.x; q2[2*j + 1] = tq.y;
            }
        }
        float lg[NTOK];
        const float* brow = g_bias + hh * (NTOK * NTOK) + n * NTOK;
        const float* mrow = mask + ((size_t)wi * NTOK + n) * NTOK;
        #pragma unroll 7
        for (int m = 0; m < NTOK; ++m) {
            const ulonglong2* krow =
                reinterpret_cast<const ulonglong2*>(ksm + m * PITCH + hh * 32);
            u64 a0 = 0, a1 = 0, a2 = 0, a3 = 0;
            #pragma unroll
            for (int j = 0; j < 8; j += 2) {
                ulonglong2 k2 = krow[j];
                fma2(a0, q2[2*j],     k2.x);
                fma2(a1, q2[2*j + 1], k2.y);
                ulonglong2 k3 = krow[j + 1];
                fma2(a2, q2[2*j + 2], k3.x);
                fma2(a3, q2[2*j + 3], k3.y);
            }
            lg[m] = hsum2(add2(add2(a0, a1), add2(a2, a3))) + brow[m] + mrow[m];
        }
        // neg softmax: sign(l) * softmax(|l|)
        float M = 0.0f;
        #pragma unroll
        for (int m = 0; m < NTOK; ++m) M = fmaxf(M, fabsf(lg[m]));
        float ssum = 0.0f;
        #pragma unroll
        for (int m = 0; m < NTOK; ++m) {
            float l = lg[m];
            float e = __expf(fabsf(l) - M);
            ssum += e;
            lg[m] = (l > 0.0f) ? e : ((l < 0.0f) ? -e : 0.0f);
        }
        const float rinv = 1.0f / ssum;

        u64 oacc[16];
        #pragma unroll
        for (int j = 0; j < 16; ++j) oacc[j] = 0;
        #pragma unroll 7
        for (int m = 0; m < NTOK; ++m) {
            const u64 p2 = dup2(lg[m]);
            const ulonglong2* vrow =
                reinterpret_cast<const ulonglong2*>(vsm + m * PITCH + hh * 32);
            #pragma unroll
            for (int j = 0; j < 8; ++j) {
                ulonglong2 v2 = vrow[j];
                fma2(oacc[2*j],     p2, v2.x);
                fma2(oacc[2*j + 1], p2, v2.y);
            }
        }
        // write O directly in (hi,lo) split form for the proj GEMM
        float2* orow = xsp + n * PITCH + hh * 32;
        #pragma unroll
        for (int j = 0; j < 16; ++j) {
            float lo, hi; upk2(oacc[j], lo, hi);
            float o0 = lo * rinv, o1 = hi * rinv;
            float h0 = tf32r(o0), h1 = tf32r(o1);
            float2 p0; p0.x = h0; p0.y = tf32r(o0 - h0);
            float2 p1; p1.x = h1; p1.y = tf32r(o1 - h1);
            orow[2*j]     = p0;
            orow[2*j + 1] = p1;
        }
    }
    __syncthreads();

    // ---- projection (tensor cores), direct store to gmem ----
    gemm64x96(xsp, 3, proj_b, 1.0f, nullptr, out + (size_t)b * (NTOK * DIMC),
              wm, wn, g, t, lane);
}

extern "C" void kernel_launch(void* const* d_in, const int* in_sizes, int n_in,
                              void* d_out, int out_size) {
    const float* x      = (const float*)d_in[0];
    const float* mask   = (const float*)d_in[1];
    const float* qkv_w  = (const float*)d_in[2];
    const float* qkv_b  = (const float*)d_in[3];
    const float* proj_w = (const float*)d_in[4];
    const float* proj_b = (const float*)d_in[5];
    const float* rpb    = (const float*)d_in[6];
    const int*   rel    = (const int*)d_in[7];
    float* out = (float*)d_out;

    cudaFuncSetAttribute(win_attn_kernel,
                         cudaFuncAttributeMaxDynamicSharedMemorySize, SMEM_BYTES);

    prep_kernel<<<144, 128>>>(rpb, rel, qkv_w, proj_w);
    win_attn_kernel<<<4096, NTHR, SMEM_BYTES>>>(x, mask, qkv_b, proj_b, out);
}

// round 16
// speedup vs baseline: 1.0022x; 1.0022x over previous
#include <cuda_runtime.h>
#include <math.h>

#define DIMC   96
#define NTOK   49
#define PITCH  100
#define NTHR   192

// smem layout (floats)
#define XSP_OFF 0        // 64 x PITCH x float2 : (hi,lo) split A tile (x, later O)
#define QS_OFF  12800    // 49 x PITCH : q
#define KS_OFF  17700    // 49 x PITCH : k
#define VS_OFF  22600    // 49 x PITCH : v
#define SMEM_FLOATS 27500
#define SMEM_BYTES  (SMEM_FLOATS * 4)

typedef unsigned long long u64;
typedef unsigned int u32;

__device__ float  g_bias[3 * NTOK * NTOK];
// [phase(4)][ks(12)][nbg(12)][lane(32)] -> (b0hi, b1hi, b0lo, b1lo)
__device__ float4 g_wfrag[4 * 12 * 12 * 32];

__device__ __forceinline__ float tf32r(float a) {
    float r; asm("cvt.rna.tf32.f32 %0, %1;" : "=f"(r) : "f"(a)); return r;
}

// ---- packed fp32x2 helpers (attention core) ----
__device__ __forceinline__ void fma2(u64& d, u64 a, u64 b) {
    asm("fma.rn.f32x2 %0, %1, %2, %0;" : "+l"(d) : "l"(a), "l"(b));
}
__device__ __forceinline__ u64 add2(u64 a, u64 b) {
    u64 d; asm("add.rn.f32x2 %0, %1, %2;" : "=l"(d) : "l"(a), "l"(b)); return d;
}
__device__ __forceinline__ float hsum2(u64 v) {
    float lo, hi; asm("mov.b64 {%0, %1}, %2;" : "=f"(lo), "=f"(hi) : "l"(v));
    return lo + hi;
}
__device__ __forceinline__ u64 dup2(float x) {
    u64 r; asm("mov.b64 %0, {%1, %1};" : "=l"(r) : "f"(x)); return r;
}
__device__ __forceinline__ void upk2(u64 v, float& lo, float& hi) {
    asm("mov.b64 {%0, %1}, %2;" : "=f"(lo), "=f"(hi) : "l"(v));
}

// ---- m16n8k8 tf32 mma, D = A*B + D ----
__device__ __forceinline__ void mma8(float c[4], const u32 a[4], u32 b0, u32 b1) {
    asm volatile(
        "mma.sync.aligned.m16n8k8.row.col.f32.tf32.tf32.f32 "
        "{%0,%1,%2,%3}, {%4,%5,%6,%7}, {%8,%9}, {%0,%1,%2,%3};"
        : "+f"(c[0]), "+f"(c[1]), "+f"(c[2]), "+f"(c[3])
        : "r"(a[0]), "r"(a[1]), "r"(a[2]), "r"(a[3]), "r"(b0), "r"(b1));
}

// ---- prep: gather rpb bias + split weights into tf32 hi/lo fragment order ----
__global__ void prep_kernel(const float* __restrict__ rpb,
                            const int* __restrict__ rel,
                            const float* __restrict__ qkv_w,
                            const float* __restrict__ proj_w) {
    int i = blockIdx.x * blockDim.x + threadIdx.x;
    if (i < NTOK * NTOK) {
        int idx = rel[i];
        #pragma unroll
        for (int h = 0; h < 3; ++h)
            g_bias[h * (NTOK * NTOK) + i] = rpb[idx * 3 + h];
    }
    if (i < 4 * 12 * 12 * 32) {
        int lane = i & 31;
        int rest = i >> 5;          // 0..575
        int nbg  = rest % 12;
        int ks   = (rest / 12) % 12;
        int p    = rest / 144;      // 0..3
        const float* W = (p < 3) ? (qkv_w + p * DIMC * DIMC) : proj_w;
        int g = lane >> 2, t = lane & 3;
        int n = nbg * 8 + g;
        int k0 = ks * 8 + t;
        float b0 = W[n * DIMC + k0];
        float b1 = W[n * DIMC + k0 + 4];
        float h0 = tf32r(b0), h1 = tf32r(b1);
        float4 v;
        v.x = h0; v.y = h1;
        v.z = tf32r(b0 - h0); v.w = tf32r(b1 - h1);
        g_wfrag[i] = v;
    }
}

// ---- one 64x96x96 GEMM on tensor cores (3xTF32); A pre-split (hi,lo) ----
__device__ __forceinline__ void gemm64x96(
    const float2* __restrict__ xsp,    // A tile 64 x PITCH float2 (hi,lo), smem
    int slice,                          // 0..3 -> g_wfrag phase
    const float* __restrict__ bias,     // 96 biases (gmem)
    float scale,
    float* __restrict__ dst_smem,       // 49 x PITCH, or null
    float* __restrict__ dst_gmem,       // rows<49, ld 96, or null
    int wm, int wn, int g, int t, int lane) {

    float acc[2][4][4];
    #pragma unroll
    for (int a = 0; a < 2; ++a)
        #pragma unroll
        for (int b = 0; b < 4; ++b)
            #pragma unroll
            for (int c = 0; c < 4; ++c) acc[a][b][c] = 0.0f;

    const float4* wf = g_wfrag + slice * (12 * 12 * 32);

    float4 bpre[4];
    #pragma unroll
    for (int nb = 0; nb < 4; ++nb)
        bpre[nb] = wf[(wn * 4 + nb) * 32 + lane];

    #pragma unroll 2
    for (int ks = 0; ks < 12; ++ks) {
        float4 bcur[4];
        #pragma unroll
        for (int nb = 0; nb < 4; ++nb) bcur[nb] = bpre[nb];
        if (ks < 11) {
            #pragma unroll
            for (int nb = 0; nb < 4; ++nb)
                bpre[nb] = wf[((ks + 1) * 12 + wn * 4 + nb) * 32 + lane];
        }
        // A fragments: rows (wm*32+mb*16)+{g, g+8}, cols ks*8+{t, t+4}; no CVT
        u32 ah[2][4], al[2][4];
        #pragma unroll
        for (int mb = 0; mb < 2; ++mb) {
            const int r = wm * 32 + mb * 16 + g;
            const float2* xp = xsp + r * PITCH + ks * 8 + t;
            float2 a0 = xp[0];
            float2 a1 = xp[8 * PITCH];
            float2 a2 = xp[4];
            float2 a3 = xp[8 * PITCH + 4];
            ah[mb][0] = __float_as_uint(a0.x); al[mb][0] = __float_as_uint(a0.y);
            ah[mb][1] = __float_as_uint(a1.x); al[mb][1] = __float_as_uint(a1.y);
            ah[mb][2] = __float_as_uint(a2.x); al[mb][2] = __float_as_uint(a2.y);
            ah[mb][3] = __float_as_uint(a3.x); al[mb][3] = __float_as_uint(a3.y);
        }
        #pragma unroll
        for (int nb = 0; nb < 4; ++nb) {
            u32 b0h = __float_as_uint(bcur[nb].x), b1h = __float_as_uint(bcur[nb].y);
            u32 b0l = __float_as_uint(bcur[nb].z), b1l = __float_as_uint(bcur[nb].w);
            #pragma unroll
            for (int mb = 0; mb < 2; ++mb) {
                mma8(acc[mb][nb], ah[mb], b0h, b1h);   // hi*hi
                mma8(acc[mb][nb], ah[mb], b0l, b1l);   // hi*lo
                mma8(acc[mb][nb], al[mb], b0h, b1h);   // lo*hi
            }
        }
    }

    // epilogue: bias add, optional scale, guarded stores (rows < 49)
    #pragma unroll
    for (int mb = 0; mb < 2; ++mb) {
        #pragma unroll
        for (int nb = 0; nb < 4; ++nb) {
            const int r0 = wm * 32 + mb * 16 + g;
            const int c0 = wn * 32 + nb * 8 + (t << 1);
            float bx = bias[c0], by = bias[c0 + 1];
            float v00 = (acc[mb][nb][0] + bx) * scale;
            float v01 = (acc[mb][nb][1] + by) * scale;
            float v10 = (acc[mb][nb][2] + bx) * scale;
            float v11 = (acc[mb][nb][3] + by) * scale;
            if (dst_smem) {
                if (r0 < NTOK)     { dst_smem[r0 * PITCH + c0] = v00; dst_smem[r0 * PITCH + c0 + 1] = v01; }
                if (r0 + 8 < NTOK) { dst_smem[(r0 + 8) * PITCH + c0] = v10; dst_smem[(r0 + 8) * PITCH + c0 + 1] = v11; }
            } else {
                if (r0 < NTOK) {
                    float2 o; o.x = v00; o.y = v01;
                    *reinterpret_cast<float2*>(dst_gmem + r0 * DIMC + c0) = o;
                }
                if (r0 + 8 < NTOK) {
                    float2 o; o.x = v10; o.y = v11;
                    *reinterpret_cast<float2*>(dst_gmem + (r0 + 8) * DIMC + c0) = o;
                }
            }
        }
    }
}

__global__ void __launch_bounds__(NTHR, 2)
win_attn_kernel(const float* __restrict__ x,
                const float* __restrict__ mask,
                const float* __restrict__ qkv_b,
                const float* __restrict__ proj_b,
                float* __restrict__ out) {
    extern __shared__ float sm[];
    float2* xsp = reinterpret_cast<float2*>(sm + XSP_OFF); // (hi,lo) A tile
    float*  qsm = sm + QS_OFF;
    float*  ksm = sm + KS_OFF;
    float*  vsm = sm + VS_OFF;

    const int b    = blockIdx.x;
    const int wi   = b & 63;
    const int tid  = threadIdx.x;
    const int wid  = tid >> 5;
    const int lane = tid & 31;
    const int g    = lane >> 2;
    const int t    = lane & 3;
    const int wm   = wid & 1;      // 0..1
    const int wn   = wid >> 1;     // 0..2

    // ---- stage x with tf32 hi/lo split (49 real rows + 15 zero pad rows) ----
    const float* xg = x + (size_t)b * (NTOK * DIMC);
    for (int i = tid; i < NTOK * DIMC; i += NTHR) {
        float v = xg[i];
        float hi = tf32r(v);
        float2 p; p.x = hi; p.y = tf32r(v - hi);
        xsp[(i / DIMC) * PITCH + (i % DIMC)] = p;
    }
    for (int i = tid; i < 15 * DIMC; i += NTHR) {
        float2 z; z.x = 0.0f; z.y = 0.0f;
        xsp[(NTOK + i / DIMC) * PITCH + (i % DIMC)] = z;
    }
    __syncthreads();

    // ---- q, k, v GEMMs (tensor cores, no in-loop CVT) ----
    const float scale = 0.17677669529663687f;  // 32^-0.5
    gemm64x96(xsp, 0, qkv_b,       scale, qsm, nullptr, wm, wn, g, t, lane);
    gemm64x96(xsp, 1, qkv_b + 96,  1.0f,  ksm, nullptr, wm, wn, g, t, lane);
    gemm64x96(xsp, 2, qkv_b + 192, 1.0f,  vsm, nullptr, wm, wn, g, t, lane);
    __syncthreads();

    // ---- attention: scalar fp32, thread (n, h) owns one query row ----
    const int n = tid & 63;
    const int hh = tid >> 6;
    if (n < NTOK) {
        // q row -> packed regs
        u64 q2[16];
        {
            const ulonglong2* qrow =
                reinterpret_cast<const ulonglong2*>(qsm + n * PITCH + hh * 32);
            #pragma unroll
            for (int j = 0; j < 8; ++j) {
                ulonglong2 tq = qrow[j];
                q2[2*j] = tq.x; q2[2*j + 1] = tq.y;
            }
        }
        float lg[NTOK];
        const float* brow = g_bias + hh * (NTOK * NTOK) + n * NTOK;
        const float* mrow = mask + ((size_t)wi * NTOK + n) * NTOK;
        #pragma unroll 7
        for (int m = 0; m < NTOK; ++m) {
            const ulonglong2* krow =
                reinterpret_cast<const ulonglong2*>(ksm + m * PITCH + hh * 32);
            u64 a0 = 0, a1 = 0, a2 = 0, a3 = 0;
            #pragma unroll
            for (int j = 0; j < 8; j += 2) {
                ulonglong2 k2 = krow[j];
                fma2(a0, q2[2*j],     k2.x);
                fma2(a1, q2[2*j + 1], k2.y);
                ulonglong2 k3 = krow[j + 1];
                fma2(a2, q2[2*j + 2], k3.x);
                fma2(a3, q2[2*j + 3], k3.y);
            }
            lg[m] = hsum2(add2(add2(a0, a1), add2(a2, a3))) + brow[m] + mrow[m];
        }
        // neg softmax: sign(l) * softmax(|l|)
        float M = 0.0f;
        #pragma unroll
        for (int m = 0; m < NTOK; ++m) M = fmaxf(M, fabsf(lg[m]));
        float ssum = 0.0f;
        #pragma unroll
        for (int m = 0; m < NTOK; ++m) {
            float l = lg[m];
            float e = __expf(fabsf(l) - M);
            ssum += e;
            lg[m] = (l > 0.0f) ? e : ((l < 0.0f) ? -e : 0.0f);
        }
        const float rinv = 1.0f / ssum;

        u64 oacc[16];
        #pragma unroll
        for (int j = 0; j < 16; ++j) oacc[j] = 0;
        #pragma unroll 7
        for (int m = 0; m < NTOK; ++m) {
            const u64 p2 = dup2(lg[m]);
            const ulonglong2* vrow =
                reinterpret_cast<const ulonglong2*>(vsm + m * PITCH + hh * 32);
            #pragma unroll
            for (int j = 0; j < 8; ++j) {
                ulonglong2 v2 = vrow[j];
                fma2(oacc[2*j],     p2, v2.x);
                fma2(oacc[2*j + 1], p2, v2.y);
            }
        }
        // write O directly in (hi,lo) split form for the proj GEMM
        float2* orow = xsp + n * PITCH + hh * 32;
        #pragma unroll
        for (int j = 0; j < 16; ++j) {
            float lo, hi; upk2(oacc[j], lo, hi);
            float o0 = lo * rinv, o1 = hi * rinv;
            float h0 = tf32r(o0), h1 = tf32r(o1);
            float2 p0; p0.x = h0; p0.y = tf32r(o0 - h0);
            float2 p1; p1.x = h1; p1.y = tf32r(o1 - h1);
            orow[2*j]     = p0;
            orow[2*j + 1] = p1;
        }
    }
    __syncthreads();

    // ---- projection (tensor cores), direct store to gmem ----
    gemm64x96(xsp, 3, proj_b, 1.0f, nullptr, out + (size_t)b * (NTOK * DIMC),
              wm, wn, g, t, lane);
}

extern "C" void kernel_launch(void* const* d_in, const int* in_sizes, int n_in,
                              void* d_out, int out_size) {
    const float* x      = (const float*)d_in[0];
    const float* mask   = (const float*)d_in[1];
    const float* qkv_w  = (const float*)d_in[2];
    const float* qkv_b  = (const float*)d_in[3];
    const float* proj_w = (const float*)d_in[4];
    const float* proj_b = (const float*)d_in[5];
    const float* rpb    = (const float*)d_in[6];
    const int*   rel    = (const int*)d_in[7];
    float* out = (float*)d_out;

    cudaFuncSetAttribute(win_attn_kernel,
                         cudaFuncAttributeMaxDynamicSharedMemorySize, SMEM_BYTES);

    prep_kernel<<<144, 128>>>(rpb, rel, qkv_w, proj_w);
    win_attn_kernel<<<4096, NTHR, SMEM_BYTES>>>(x, mask, qkv_b, proj_b, out);
}

// round 17
// speedup vs baseline: 1.0057x; 1.0034x over previous
#include <cuda_runtime.h>
#include <math.h>

#define DIMC   96
#define NTOK   49
#define PITCH  100
#define NTHR   192

// smem layout (floats)
#define XSP_OFF 0        // 64 x PITCH x float2 : (hi,lo) split A tile (x, later O)
#define QS_OFF  12800    // 49 x PITCH : q
#define KS_OFF  17700    // 49 x PITCH : k
#define VS_OFF  22600    // 49 x PITCH : v
#define SMEM_FLOATS 27500
#define SMEM_BYTES  (SMEM_FLOATS * 4)

typedef unsigned long long u64;
typedef unsigned int u32;

__device__ float  g_bias[3 * NTOK * NTOK];
// [phase(4)][ks(12)][nbg(12)][lane(32)] -> (b0hi, b1hi, b0lo, b1lo)
__device__ float4 g_wfrag[4 * 12 * 12 * 32];

__device__ __forceinline__ float tf32r(float a) {
    float r; asm("cvt.rna.tf32.f32 %0, %1;" : "=f"(r) : "f"(a)); return r;
}

// ---- packed fp32x2 helpers (attention core) ----
__device__ __forceinline__ void fma2(u64& d, u64 a, u64 b) {
    asm("fma.rn.f32x2 %0, %1, %2, %0;" : "+l"(d) : "l"(a), "l"(b));
}
__device__ __forceinline__ u64 add2(u64 a, u64 b) {
    u64 d; asm("add.rn.f32x2 %0, %1, %2;" : "=l"(d) : "l"(a), "l"(b)); return d;
}
__device__ __forceinline__ float hsum2(u64 v) {
    float lo, hi; asm("mov.b64 {%0, %1}, %2;" : "=f"(lo), "=f"(hi) : "l"(v));
    return lo + hi;
}
__device__ __forceinline__ u64 dup2(float x) {
    u64 r; asm("mov.b64 %0, {%1, %1};" : "=l"(r) : "f"(x)); return r;
}
__device__ __forceinline__ void upk2(u64 v, float& lo, float& hi) {
    asm("mov.b64 {%0, %1}, %2;" : "=f"(lo), "=f"(hi) : "l"(v));
}

// ---- m16n8k8 tf32 mma, D = A*B + D ----
__device__ __forceinline__ void mma8(float c[4], const u32 a[4], u32 b0, u32 b1) {
    asm volatile(
        "mma.sync.aligned.m16n8k8.row.col.f32.tf32.tf32.f32 "
        "{%0,%1,%2,%3}, {%4,%5,%6,%7}, {%8,%9}, {%0,%1,%2,%3};"
        : "+f"(c[0]), "+f"(c[1]), "+f"(c[2]), "+f"(c[3])
        : "r"(a[0]), "r"(a[1]), "r"(a[2]), "r"(a[3]), "r"(b0), "r"(b1));
}

// ---- prep: gather rpb bias + split weights into tf32 hi/lo fragment order ----
__global__ void prep_kernel(const float* __restrict__ rpb,
                            const int* __restrict__ rel,
                            const float* __restrict__ qkv_w,
                            const float* __restrict__ proj_w) {
    int i = blockIdx.x * blockDim.x + threadIdx.x;
    if (i < NTOK * NTOK) {
        int idx = rel[i];
        #pragma unroll
        for (int h = 0; h < 3; ++h)
            g_bias[h * (NTOK * NTOK) + i] = rpb[idx * 3 + h];
    }
    if (i < 4 * 12 * 12 * 32) {
        int lane = i & 31;
        int rest = i >> 5;          // 0..575
        int nbg  = rest % 12;
        int ks   = (rest / 12) % 12;
        int p    = rest / 144;      // 0..3
        const float* W = (p < 3) ? (qkv_w + p * DIMC * DIMC) : proj_w;
        int g = lane >> 2, t = lane & 3;
        int n = nbg * 8 + g;
        int k0 = ks * 8 + t;
        float b0 = W[n * DIMC + k0];
        float b1 = W[n * DIMC + k0 + 4];
        float h0 = tf32r(b0), h1 = tf32r(b1);
        float4 v;
        v.x = h0; v.y = h1;
        v.z = tf32r(b0 - h0); v.w = tf32r(b1 - h1);
        g_wfrag[i] = v;
    }
}

// ---- one 64x96x96 GEMM on tensor cores (3xTF32); A pre-split (hi,lo) ----
__device__ __forceinline__ void gemm64x96(
    const float2* __restrict__ xsp,    // A tile 64 x PITCH float2 (hi,lo), smem
    int slice,                          // 0..3 -> g_wfrag phase
    const float* __restrict__ bias,     // 96 biases (gmem)
    float scale,
    float* __restrict__ dst_smem,       // 49 x PITCH, or null
    float* __restrict__ dst_gmem,       // rows<49, ld 96, or null
    int wm, int wn, int g, int t, int lane) {

    float acc[2][4][4];
    #pragma unroll
    for (int a = 0; a < 2; ++a)
        #pragma unroll
        for (int b = 0; b < 4; ++b)
            #pragma unroll
            for (int c = 0; c < 4; ++c) acc[a][b][c] = 0.0f;

    const float4* wf = g_wfrag + slice * (12 * 12 * 32);

    float4 bpre[4];
    #pragma unroll
    for (int nb = 0; nb < 4; ++nb)
        bpre[nb] = wf[(wn * 4 + nb) * 32 + lane];

    #pragma unroll 2
    for (int ks = 0; ks < 12; ++ks) {
        float4 bcur[4];
        #pragma unroll
        for (int nb = 0; nb < 4; ++nb) bcur[nb] = bpre[nb];
        if (ks < 11) {
            #pragma unroll
            for (int nb = 0; nb < 4; ++nb)
                bpre[nb] = wf[((ks + 1) * 12 + wn * 4 + nb) * 32 + lane];
        }
        // A fragments: rows (wm*32+mb*16)+{g, g+8}, cols ks*8+{t, t+4}; no CVT
        u32 ah[2][4], al[2][4];
        #pragma unroll
        for (int mb = 0; mb < 2; ++mb) {
            const int r = wm * 32 + mb * 16 + g;
            const float2* xp = xsp + r * PITCH + ks * 8 + t;
            float2 a0 = xp[0];
            float2 a1 = xp[8 * PITCH];
            float2 a2 = xp[4];
            float2 a3 = xp[8 * PITCH + 4];
            ah[mb][0] = __float_as_uint(a0.x); al[mb][0] = __float_as_uint(a0.y);
            ah[mb][1] = __float_as_uint(a1.x); al[mb][1] = __float_as_uint(a1.y);
            ah[mb][2] = __float_as_uint(a2.x); al[mb][2] = __float_as_uint(a2.y);
            ah[mb][3] = __float_as_uint(a3.x); al[mb][3] = __float_as_uint(a3.y);
        }
        #pragma unroll
        for (int nb = 0; nb < 4; ++nb) {
            u32 b0h = __float_as_uint(bcur[nb].x), b1h = __float_as_uint(bcur[nb].y);
            u32 b0l = __float_as_uint(bcur[nb].z), b1l = __float_as_uint(bcur[nb].w);
            #pragma unroll
            for (int mb = 0; mb < 2; ++mb) {
                mma8(acc[mb][nb], ah[mb], b0h, b1h);   // hi*hi
                mma8(acc[mb][nb], ah[mb], b0l, b1l);   // hi*lo
                mma8(acc[mb][nb], al[mb], b0h, b1h);   // lo*hi
            }
        }
    }

    // epilogue: bias add, optional scale, guarded stores (rows < 49)
    #pragma unroll
    for (int mb = 0; mb < 2; ++mb) {
        #pragma unroll
        for (int nb = 0; nb < 4; ++nb) {
            const int r0 = wm * 32 + mb * 16 + g;
            const int c0 = wn * 32 + nb * 8 + (t << 1);
            float bx = bias[c0], by = bias[c0 + 1];
            float v00 = (acc[mb][nb][0] + bx) * scale;
            float v01 = (acc[mb][nb][1] + by) * scale;
            float v10 = (acc[mb][nb][2] + bx) * scale;
            float v11 = (acc[mb][nb][3] + by) * scale;
            if (dst_smem) {
                if (r0 < NTOK)     { dst_smem[r0 * PITCH + c0] = v00; dst_smem[r0 * PITCH + c0 + 1] = v01; }
                if (r0 + 8 < NTOK) { dst_smem[(r0 + 8) * PITCH + c0] = v10; dst_smem[(r0 + 8) * PITCH + c0 + 1] = v11; }
            } else {
                if (r0 < NTOK) {
                    float2 o; o.x = v00; o.y = v01;
                    *reinterpret_cast<float2*>(dst_gmem + r0 * DIMC + c0) = o;
                }
                if (r0 + 8 < NTOK) {
                    float2 o; o.x = v10; o.y = v11;
                    *reinterpret_cast<float2*>(dst_gmem + (r0 + 8) * DIMC + c0) = o;
                }
            }
        }
    }
}

__global__ void __launch_bounds__(NTHR, 2)
win_attn_kernel(const float* __restrict__ x,
                const float* __restrict__ mask,
                const float* __restrict__ qkv_b,
                const float* __restrict__ proj_b,
                float* __restrict__ out) {
    extern __shared__ float sm[];
    float2* xsp = reinterpret_cast<float2*>(sm + XSP_OFF); // (hi,lo) A tile
    float*  qsm = sm + QS_OFF;
    float*  ksm = sm + KS_OFF;
    float*  vsm = sm + VS_OFF;

    const int b    = blockIdx.x;
    const int wi   = b & 63;
    const int tid  = threadIdx.x;
    const int wid  = tid >> 5;
    const int lane = tid & 31;
    const int g    = lane >> 2;
    const int t    = lane & 3;
    const int wm   = wid & 1;      // 0..1
    const int wn   = wid >> 1;     // 0..2

    // ---- stage x with tf32 hi/lo split (49 real rows + 15 zero pad rows) ----
    const float* xg = x + (size_t)b * (NTOK * DIMC);
    for (int i = tid; i < NTOK * DIMC; i += NTHR) {
        float v = xg[i];
        float hi = tf32r(v);
        float2 p; p.x = hi; p.y = tf32r(v - hi);
        xsp[(i / DIMC) * PITCH + (i % DIMC)] = p;
    }
    for (int i = tid; i < 15 * DIMC; i += NTHR) {
        float2 z; z.x = 0.0f; z.y = 0.0f;
        xsp[(NTOK + i / DIMC) * PITCH + (i % DIMC)] = z;
    }
    __syncthreads();

    // ---- q, k, v GEMMs (tensor cores, no in-loop CVT) ----
    const float scale = 0.17677669529663687f;  // 32^-0.5
    gemm64x96(xsp, 0, qkv_b,       scale, qsm, nullptr, wm, wn, g, t, lane);
    gemm64x96(xsp, 1, qkv_b + 96,  1.0f,  ksm, nullptr, wm, wn, g, t, lane);
    gemm64x96(xsp, 2, qkv_b + 192, 1.0f,  vsm, nullptr, wm, wn, g, t, lane);
    __syncthreads();

    // ---- attention: scalar fp32, thread (n, h) owns one query row ----
    const int n = tid & 63;
    const int hh = tid >> 6;
    if (n < NTOK) {
        // q row -> packed regs
        u64 q2[16];
        {
            const ulonglong2* qrow =
                reinterpret_cast<const ulonglong2*>(qsm + n * PITCH + hh * 32);
            #pragma unroll
            for (int j = 0; j < 8; ++j) {
                ulonglong2 tq = qrow[j];
                q2[2*j] = tq.x; q2[2*j + 1] = tq.y;
            }
        }
        float lg[NTOK];
        const float* brow = g_bias + hh * (NTOK * NTOK) + n * NTOK;
        const float* mrow = mask + ((size_t)wi * NTOK + n) * NTOK;
        #pragma unroll 7
        for (int m = 0; m < NTOK; ++m) {
            const ulonglong2* krow =
                reinterpret_cast<const ulonglong2*>(ksm + m * PITCH + hh * 32);
            u64 a0 = 0, a1 = 0, a2 = 0, a3 = 0;
            #pragma unroll
            for (int j = 0; j < 8; j += 2) {
                ulonglong2 k2 = krow[j];
                fma2(a0, q2[2*j],     k2.x);
                fma2(a1, q2[2*j + 1], k2.y);
                ulonglong2 k3 = krow[j + 1];
                fma2(a2, q2[2*j + 2], k3.x);
                fma2(a3, q2[2*j + 3], k3.y);
            }
            lg[m] = hsum2(add2(add2(a0, a1), add2(a2, a3))) + brow[m] + mrow[m];
        }
        // neg softmax: sign(l) * softmax(|l|)
        float M = 0.0f;
        #pragma unroll
        for (int m = 0; m < NTOK; ++m) M = fmaxf(M, fabsf(lg[m]));
        float ssum = 0.0f;
        #pragma unroll
        for (int m = 0; m < NTOK; ++m) {
            float l = lg[m];
            float e = __expf(fabsf(l) - M);
            ssum += e;
            lg[m] = (l > 0.0f) ? e : ((l < 0.0f) ? -e : 0.0f);
        }
        const float rinv = 1.0f / ssum;

        u64 oacc[16];
        #pragma unroll
        for (int j = 0; j < 16; ++j) oacc[j] = 0;
        #pragma unroll 7
        for (int m = 0; m < NTOK; ++m) {
            const u64 p2 = dup2(lg[m]);
            const ulonglong2* vrow =
                reinterpret_cast<const ulonglong2*>(vsm + m * PITCH + hh * 32);
            #pragma unroll
            for (int j = 0; j < 8; ++j) {
                ulonglong2 v2 = vrow[j];
                fma2(oacc[2*j],     p2, v2.x);
                fma2(oacc[2*j + 1], p2, v2.y);
            }
        }
        // write O directly in (hi,lo) split form for the proj GEMM
        float2* orow = xsp + n * PITCH + hh * 32;
        #pragma unroll
        for (int j = 0; j < 16; ++j) {
            float lo, hi; upk2(oacc[j], lo, hi);
            float o0 = lo * rinv, o1 = hi * rinv;
            float h0 = tf32r(o0), h1 = tf32r(o1);
            float2 p0; p0.x = h0; p0.y = tf32r(o0 - h0);
            float2 p1; p1.x = h1; p1.y = tf32r(o1 - h1);
            orow[2*j]     = p0;
            orow[2*j + 1] = p1;
        }
    }
    __syncthreads();

    // ---- projection (tensor cores), direct store to gmem ----
    gemm64x96(xsp, 3, proj_b, 1.0f, nullptr, out + (size_t)b * (NTOK * DIMC),
              wm, wn, g, t, lane);
}

extern "C" void kernel_launch(void* const* d_in, const int* in_sizes, int n_in,
                              void* d_out, int out_size) {
    const float* x      = (const float*)d_in[0];
    const float* mask   = (const float*)d_in[1];
    const float* qkv_w  = (const float*)d_in[2];
    const float* qkv_b  = (const float*)d_in[3];
    const float* proj_w = (const float*)d_in[4];
    const float* proj_b = (const float*)d_in[5];
    const float* rpb    = (const float*)d_in[6];
    const int*   rel    = (const int*)d_in[7];
    float* out = (float*)d_out;

    cudaFuncSetAttribute(win_attn_kernel,
                         cudaFuncAttributeMaxDynamicSharedMemorySize, SMEM_BYTES);

    prep_kernel<<<144, 128>>>(rpb, rel, qkv_w, proj_w);
    win_attn_kernel<<<4096, NTHR, SMEM_BYTES>>>(x, mask, qkv_b, proj_b, out);
}